// round 5
// baseline (speedup 1.0000x reference)
#include <cuda_runtime.h>
#include <cuda_fp16.h>
#include <cuda.h>
#include <cstdint>
#include <math.h>

// ---------------- problem constants ----------------
#define BB   1024
#define UU   2048
#define GK   4096            // GEMM K = 2U
#define GN   8192            // GEMM N = 4U

// ---------------- arch gate ----------------
#if defined(__CUDA_ARCH__) && (defined(__CUDA_ARCH_FEAT_SM103_ALL) || \
                               defined(__CUDA_ARCH_FEAT_SM100_ALL) || \
                               defined(__CUDA_ARCH_FEAT_SM101_ALL))
#define HAS_TCGEN05 1
#else
#define HAS_TCGEN05 0
#endif

// ---------------- GEMM tiling ----------------
#define BM   256
#define BN   256
#define BK   64
#define NC   (GK / BK)       // 64 chunks
#define NSTAGE 3
#define CLUSTER_X 4

#define SMEM_TMEM_PTR 0
#define SMEM_FULL0    32     // full[s] = 32 + 8s
#define SMEM_DONE0    64     // done[s] = 64 + 8s
#define SMEM_STAGE0   1024
#define STAGE_BYTES   65536
#define STAGE_B_OFF   32768
#define SMEM_BYTES    (1024 + NSTAGE * STAGE_BYTES)

// idesc kind::f16: F32 accum, f16 inputs, N=128, M=128
#define MMA_IDESC  ((1u << 4) | (16u << 17) | (8u << 24))

// ---------------- device scratch ----------------
__device__ __half g_Af16[(size_t)BB * GK];        // [1024][4096] packed xh fp16
__device__ __half g_Wt  [(size_t)GN * GK];        // [8192][4096] fp16 K-major, gate-permuted

// ---------------- generic helpers ----------------
__device__ __forceinline__ uint32_t smem_u32(const void* p) {
    uint32_t a;
    asm("{ .reg .u64 t; cvta.to.shared.u64 t, %1; cvt.u32.u64 %0, t; }" : "=r"(a) : "l"(p));
    return a;
}
#define SW128(off) ((off) ^ (((off) >> 3) & 0x70))
__device__ __forceinline__ float sigmoidf_(float v) { return 1.f / (1.f + expf(-v)); }

// ================= preprocessing =================

__global__ void pack_a_kernel(const float* __restrict__ x, const float* __restrict__ h) {
    const int gi = blockIdx.x * blockDim.x + threadIdx.x;
    const int b  = gi >> 10;
    const int k  = (gi & 1023) * 4;
    const int ksp = k >> 11;
    const int d   = k & 2047;
    const float* src = (d < 1024) ? (x + (size_t)b * UU + ksp * 1024 + d)
                                  : (h + (size_t)b * UU + ksp * 1024 + (d - 1024));
    const float4 v = *reinterpret_cast<const float4*>(src);
    __half2 p0 = __floats2half2_rn(v.x, v.y);
    __half2 p1 = __floats2half2_rn(v.z, v.w);
    uint2 o;
    o.x = *reinterpret_cast<uint32_t*>(&p0);
    o.y = *reinterpret_cast<uint32_t*>(&p1);
    *reinterpret_cast<uint2*>(&g_Af16[(size_t)b * GK + k]) = o;
}

// W [ksp][nsp][d][f] fp32 -> Wt[n'][k] fp16 with gate permute n' = nsp*4096 + uu*4 + gate
__global__ void transpose_w_kernel(const float* __restrict__ W) {
    __shared__ float tile[32][33];
    const int ksp = blockIdx.z >> 1, nsp = blockIdx.z & 1;
    const int dBase = blockIdx.y * 32, fBase = blockIdx.x * 32;
    const float* src = W + ((size_t)(ksp * 2 + nsp) * 2048 + dBase) * 4096 + fBase;
    #pragma unroll
    for (int j = 0; j < 4; ++j) {
        const int r = threadIdx.y * 4 + j;
        tile[r][threadIdx.x] = src[(size_t)r * 4096 + threadIdx.x];
    }
    __syncthreads();
    const int gate = fBase >> 10;
    const int uu0  = fBase & 1023;
    #pragma unroll
    for (int j = 0; j < 4; ++j) {
        const int r = threadIdx.y * 4 + j;
        const int np = nsp * 4096 + (uu0 + r) * 4 + gate;
        g_Wt[(size_t)np * GK + ksp * 2048 + dBase + threadIdx.x] =
            __float2half_rn(tile[threadIdx.x][r]);
    }
}

// ================= arch-specific helpers =================
#if HAS_TCGEN05
__device__ __forceinline__ uint32_t elect_one() {
    uint32_t pred;
    asm volatile("{\n\t.reg .pred p;\n\telect.sync _|p, 0xFFFFFFFF;\n\t"
                 "selp.b32 %0, 1, 0, p;\n\t}" : "=r"(pred));
    return pred;
}
__device__ __forceinline__ uint32_t cl_rank() {
    uint32_t r; asm("mov.u32 %0, %%cluster_ctarank;" : "=r"(r)); return r;
}
#define DESC_BASE ((uint64_t(2) << 61) | (uint64_t(1) << 46) | (uint64_t(64) << 32) | (uint64_t(1) << 16))
#define MK_DESC(addr) (DESC_BASE | ((uint64_t)((addr) >> 4) & 0x3FFF))

__device__ __forceinline__ void mma_f16_ss(uint32_t d, uint64_t ad, uint64_t bd,
                                           uint32_t idesc, uint32_t en) {
    asm volatile(
        "{\n\t.reg .pred p;\n\tsetp.ne.u32 p, %4, 0;\n\t"
        "tcgen05.mma.cta_group::1.kind::f16 [%0], %1, %2, %3, {%5,%5,%5,%5}, p;\n\t}"
        :: "r"(d), "l"(ad), "l"(bd), "r"(idesc), "r"(en), "r"(0u) : "memory");
}
#define MBAR_INIT(a, c)  asm volatile("mbarrier.init.shared.b64 [%0], %1;" :: "r"(a), "r"(c) : "memory")
#define MBAR_INVAL(a)    asm volatile("mbarrier.inval.shared.b64 [%0];" :: "r"(a) : "memory")
#define MBAR_EXPECT_TX(a, n) asm volatile("mbarrier.arrive.expect_tx.shared.b64 _, [%0], %1;" :: "r"(a), "r"(n) : "memory")
#define TC_COMMIT_MC(a, mask) asm volatile( \
    "tcgen05.commit.cta_group::1.mbarrier::arrive::one.shared::cluster.multicast::cluster.b64 [%0], %1;" \
    :: "r"(a), "h"((uint16_t)(mask)) : "memory")
#define TC_ALLOC(sa, n)  asm volatile("tcgen05.alloc.cta_group::1.sync.aligned.shared::cta.b32 [%0], %1;" :: "r"(sa), "r"(n) : "memory")
#define TC_DEALLOC(t, n) asm volatile("tcgen05.dealloc.cta_group::1.sync.aligned.b32 %0, %1;" :: "r"(t), "r"(n))
#define TC_RELINQ()      asm volatile("tcgen05.relinquish_alloc_permit.cta_group::1.sync.aligned;")
#define TC_FENCE_AFTER() asm volatile("tcgen05.fence::after_thread_sync;" ::: "memory")
#define TC_WAIT_LD()     asm volatile("tcgen05.wait::ld.sync.aligned;" ::: "memory")
#define FENCE_ASYNC()    asm volatile("fence.proxy.async.shared::cta;" ::: "memory")
#define CLUSTER_SYNC()   do { \
    asm volatile("barrier.cluster.arrive.aligned;" ::: "memory"); \
    asm volatile("barrier.cluster.wait.aligned;" ::: "memory"); } while (0)

__device__ __forceinline__ void mbar_wait(uint32_t mbar, uint32_t parity) {
    asm volatile(
        "{\n\t.reg .pred P;\n\t"
        "W%=:\n\t"
        "mbarrier.try_wait.parity.acquire.cta.shared::cta.b64 P, [%0], %1, 0x989680;\n\t"
        "@P bra.uni D%=;\n\t"
        "bra.uni W%=;\n\t"
        "D%=:\n\t}"
        :: "r"(mbar), "r"(parity) : "memory");
}
__device__ __forceinline__ void cp16(uint32_t saddr, const void* g) {
    asm volatile("cp.async.cg.shared.global [%0], [%1], 16;" :: "r"(saddr), "l"(g) : "memory");
}
#define CP_COMMIT() asm volatile("cp.async.commit_group;" ::: "memory")

__device__ __forceinline__ void tma2d_mc(uint32_t dst, const void* tmap,
                                         int cx, int cy, uint32_t mbar, uint16_t mask) {
    asm volatile(
        "cp.async.bulk.tensor.2d.shared::cluster.global.tile.mbarrier::complete_tx::bytes.multicast::cluster "
        "[%0], [%1, {%2, %3}], [%4], %5;"
        :: "r"(dst), "l"(tmap), "r"(cx), "r"(cy), "r"(mbar), "h"(mask) : "memory");
}

__device__ __forceinline__ void ldtm32(uint32_t* r, uint32_t addr) {
    asm volatile(
        "tcgen05.ld.sync.aligned.32x32b.x32.b32 "
        "{%0,%1,%2,%3,%4,%5,%6,%7,%8,%9,%10,%11,%12,%13,%14,%15,"
        "%16,%17,%18,%19,%20,%21,%22,%23,%24,%25,%26,%27,%28,%29,%30,%31}, [%32];"
        : "=r"(r[0]), "=r"(r[1]), "=r"(r[2]), "=r"(r[3]), "=r"(r[4]), "=r"(r[5]), "=r"(r[6]), "=r"(r[7]),
          "=r"(r[8]), "=r"(r[9]), "=r"(r[10]), "=r"(r[11]), "=r"(r[12]), "=r"(r[13]), "=r"(r[14]), "=r"(r[15]),
          "=r"(r[16]), "=r"(r[17]), "=r"(r[18]), "=r"(r[19]), "=r"(r[20]), "=r"(r[21]), "=r"(r[22]), "=r"(r[23]),
          "=r"(r[24]), "=r"(r[25]), "=r"(r[26]), "=r"(r[27]), "=r"(r[28]), "=r"(r[29]), "=r"(r[30]), "=r"(r[31])
        : "r"(addr));
}
#endif

// ================= GEMM + fused gates =================
// grid (4, 32), cluster (4,1,1) along x: 4 CTAs (different rowBase) share one B panel.
__global__ __launch_bounds__(256, 1) __cluster_dims__(CLUSTER_X, 1, 1)
void lstm_gemm_tc(const __grid_constant__ CUtensorMap tmapB,
                  const float* __restrict__ c, float* __restrict__ out) {
#if HAS_TCGEN05
    extern __shared__ char smem_raw[];
    const uint32_t sbase = smem_u32(smem_raw);
    const int tid  = threadIdx.x;
    const int warp = tid >> 5;
    const int lane = tid & 31;
    const uint32_t rank = cl_rank();

    const int rowBase = blockIdx.x * BM;
    const int colBase = blockIdx.y * BN;

    if (warp == 0) { TC_ALLOC(sbase + SMEM_TMEM_PTR, 512); }
    else           { TC_RELINQ(); }
    __syncthreads();
    uint32_t tmem_base;
    asm volatile("ld.shared.b32 %0, [%1];" : "=r"(tmem_base) : "r"(sbase + SMEM_TMEM_PTR));

    if (tid == 0) {
        #pragma unroll
        for (int s = 0; s < NSTAGE; ++s) {
            MBAR_INIT(sbase + SMEM_FULL0 + 8 * s, 1);          // expect_tx re-arms count each round
            MBAR_INIT(sbase + SMEM_DONE0 + 8 * s, CLUSTER_X);  // 4 commits (one per CTA)
        }
    }
    __syncthreads();
    CLUSTER_SYNC();   // barriers visible cluster-wide before any multicast traffic

    const __half* Aglob = g_Af16 + (size_t)rowBase * GK;

    // ---- A: per-CTA cp.async (8 x 16B granules per thread per chunk) ----
    #define LOAD_A(CH) do {                                                            \
        const int kOff = (CH) * BK;                                                    \
        const uint32_t stA = sbase + SMEM_STAGE0 + ((CH) % NSTAGE) * STAGE_BYTES;      \
        _Pragma("unroll")                                                              \
        for (int j = 0; j < 8; ++j) {                                                  \
            const int idx = tid + 256 * j;                                             \
            const int row = idx >> 3, kg = idx & 7;                                    \
            const uint32_t so = SW128((uint32_t)(row * 128 + kg * 16));                \
            cp16(stA + so, Aglob + (size_t)row * GK + kOff + kg * 8);                  \
        }                                                                              \
        CP_COMMIT();                                                                   \
    } while (0)

    // ---- B: cooperative-sliced TMA multicast (elected thread only) ----
    #define LOAD_B(CH) do {                                                            \
        const uint32_t s = (CH) % NSTAGE;                                              \
        const uint32_t fullb = sbase + SMEM_FULL0 + 8 * s;                             \
        const uint32_t stB = sbase + SMEM_STAGE0 + s * STAGE_BYTES + STAGE_B_OFF;      \
        MBAR_EXPECT_TX(fullb, (uint32_t)32768);                                        \
        tma2d_mc(stB + rank * 8192, &tmapB, (CH) * BK, colBase + (int)rank * 64,       \
                 fullb, (uint16_t)0xF);                                                \
    } while (0)

    // preload chunks 0..2 (3 fresh stages; no done-wait needed)
    LOAD_A(0);
    LOAD_A(1);
    if (warp == 0 && elect_one()) { LOAD_B(0); LOAD_B(1); LOAD_B(2); }
    // NOTE: A(2) issued inside the loop at it=0 (keeps cp.async group accounting simple)

    for (int it = 0; it < NC; ++it) {
        // A of chunk it arrived (<=1 newer group pending)
        if (it == NC - 1) { asm volatile("cp.async.wait_group 0;" ::: "memory"); }
        else              { asm volatile("cp.async.wait_group 1;" ::: "memory"); }
        __syncthreads();

        if (warp == 0 && elect_one()) {
            // B of chunk it arrived (4 multicast slices -> 32KB tx)
            mbar_wait(sbase + SMEM_FULL0 + 8 * (it % NSTAGE), (uint32_t)((it / 3) & 1));
            FENCE_ASYNC();
            const uint32_t st = sbase + SMEM_STAGE0 + (it % NSTAGE) * STAGE_BYTES;
            const uint64_t aD = MK_DESC(st);
            const uint64_t bD = MK_DESC(st + STAGE_B_OFF);
            #pragma unroll
            for (int m = 0; m < 2; ++m)
                #pragma unroll
                for (int hh = 0; hh < 2; ++hh) {
                    const uint32_t dcol = tmem_base + m * 256 + hh * 128;
                    #pragma unroll
                    for (int ks = 0; ks < 4; ++ks)
                        mma_f16_ss(dcol, aD + m * 1024 + ks * 2, bD + hh * 1024 + ks * 2,
                                   MMA_IDESC, (uint32_t)(it > 0 || ks > 0));
                }
            // signal "stage (it%3) consumed" to ALL cluster CTAs
            TC_COMMIT_MC(sbase + SMEM_DONE0 + 8 * (it % NSTAGE), 0xF);
        }

        // prefetch chunk it+2 into stage (it+2)%3
        {
            const int cc = it + 2;
            if (cc < NC) {
                if (cc >= 3) {
                    // previous occupant cc-3: all 4 CTAs' MMAs must be done before
                    // anyone (local cp.async OR any peer's multicast TMA) overwrites it
                    mbar_wait(sbase + SMEM_DONE0 + 8 * (cc % NSTAGE),
                              (uint32_t)(((cc - 3) / 3) & 1));
                }
                LOAD_A(cc);
                if (warp == 0 && elect_one() && cc >= 3) LOAD_B(cc);
            }
        }
    }
    #undef LOAD_A
    #undef LOAD_B

    // all MMAs done cluster-wide: chunk 63 is stage 0's 22nd occupant -> parity 1
    mbar_wait(sbase + SMEM_DONE0, 1u);
    TC_FENCE_AFTER();

    // ---- fused gate epilogue ----
    {
        const int m   = warp >> 2;
        const int sub = warp & 3;
        const int b   = rowBase + m * 128 + sub * 32 + lane;
        const int nsp    = colBase >> 12;
        const int uuBase = (colBase & 4095) >> 2;
        const float* cRow = c + (size_t)b * UU;
        float* outH = out + (size_t)b * UU;
        float* outC = out + (size_t)BB * UU + (size_t)b * UU;

        uint32_t regs[32];
        #pragma unroll
        for (int cb = 0; cb < 8; ++cb) {
            ldtm32(regs, tmem_base + m * 256 + cb * 32);
            TC_WAIT_LD();
            const int u0 = nsp * 1024 + uuBase + cb * 8;
            float cArr[8], hArr[8], nArr[8];
            *reinterpret_cast<float4*>(&cArr[0]) = *reinterpret_cast<const float4*>(cRow + u0);
            *reinterpret_cast<float4*>(&cArr[4]) = *reinterpret_cast<const float4*>(cRow + u0 + 4);
            #pragma unroll
            for (int j = 0; j < 8; ++j) {
                const float ig = sigmoidf_(__uint_as_float(regs[4 * j + 0]));
                const float fg = sigmoidf_(__uint_as_float(regs[4 * j + 1]));
                const float gg = tanhf(__uint_as_float(regs[4 * j + 2]));
                const float og = sigmoidf_(__uint_as_float(regs[4 * j + 3]));
                const float nc = fg * cArr[j] + ig * gg;
                nArr[j] = nc;
                hArr[j] = og * tanhf(nc);
            }
            *reinterpret_cast<float4*>(outH + u0)     = *reinterpret_cast<float4*>(&hArr[0]);
            *reinterpret_cast<float4*>(outH + u0 + 4) = *reinterpret_cast<float4*>(&hArr[4]);
            *reinterpret_cast<float4*>(outC + u0)     = *reinterpret_cast<float4*>(&nArr[0]);
            *reinterpret_cast<float4*>(outC + u0 + 4) = *reinterpret_cast<float4*>(&nArr[4]);
        }
    }

    __syncthreads();
    if (tid == 0) {
        #pragma unroll
        for (int s = 0; s < NSTAGE; ++s) {
            MBAR_INVAL(sbase + SMEM_FULL0 + 8 * s);
            MBAR_INVAL(sbase + SMEM_DONE0 + 8 * s);
        }
    }
    __syncthreads();
    if (warp == 0) { TC_DEALLOC(tmem_base, 512); }
    CLUSTER_SYNC();   // no CTA exits while peer multicast may still target its smem

#else
    // ===== baseline-arch fallback (compile-correct; not selected on sm_103a) =====
    const int tid = threadIdx.x;
    const int rowBase = blockIdx.x * BM;
    const int colBase = blockIdx.y * BN;
    const int nsp    = colBase >> 12;
    const int uuBase = (colBase & 4095) >> 2;
    const int b = rowBase + tid;
    const __half* arow = g_Af16 + (size_t)b * GK;
    for (int j = 0; j < 64; ++j) {
        const __half* brow = g_Wt + (size_t)(colBase + j * 4) * GK;
        float acc[4] = {0.f, 0.f, 0.f, 0.f};
        for (int k = 0; k < GK; ++k) {
            const float a = __half2float(arow[k]);
            acc[0] += a * __half2float(brow[k]);
            acc[1] += a * __half2float(brow[(size_t)GK + k]);
            acc[2] += a * __half2float(brow[(size_t)2 * GK + k]);
            acc[3] += a * __half2float(brow[(size_t)3 * GK + k]);
        }
        const int u = nsp * 1024 + uuBase + j;
        const float ig = sigmoidf_(acc[0]);
        const float fg = sigmoidf_(acc[1]);
        const float gg = tanhf(acc[2]);
        const float og = sigmoidf_(acc[3]);
        const float cin = c[(size_t)b * UU + u];
        const float nc = fg * cin + ig * gg;
        out[(size_t)b * UU + u] = og * tanhf(nc);
        out[(size_t)BB * UU + (size_t)b * UU + u] = nc;
    }
#endif
}

// ================= launch =================
typedef CUresult (*PFN_encodeTiled_t)(
    CUtensorMap*, CUtensorMapDataType, cuuint32_t, void*,
    const cuuint64_t*, const cuuint64_t*, const cuuint32_t*, const cuuint32_t*,
    CUtensorMapInterleave, CUtensorMapSwizzle, CUtensorMapL2promotion,
    CUtensorMapFloatOOBfill);

extern "C" void kernel_launch(void* const* d_in, const int* in_sizes, int n_in,
                              void* d_out, int out_size) {
    const float* x = (const float*)d_in[0];
    const float* h = (const float*)d_in[1];
    const float* c = (const float*)d_in[2];
    const float* W = (const float*)d_in[3];
    float* out = (float*)d_out;

    cudaFuncSetAttribute(lstm_gemm_tc, cudaFuncAttributeMaxDynamicSharedMemorySize, SMEM_BYTES);

    // Build the B tensormap (Wt: [N=8192][K=4096] fp16 row-major, box [64k x 64n], SW128).
    CUtensorMap tmapB;
    {
        void* wtPtr = nullptr;
        cudaGetSymbolAddress(&wtPtr, g_Wt);
        void* fn = nullptr;
        cudaDriverEntryPointQueryResult qres;
        cudaGetDriverEntryPoint("cuTensorMapEncodeTiled", &fn, cudaEnableDefault, &qres);
        PFN_encodeTiled_t enc = (PFN_encodeTiled_t)fn;
        cuuint64_t dims[2]    = {GK, GN};                    // dim0 = k (contiguous), dim1 = n
        cuuint64_t strides[1] = {(cuuint64_t)GK * 2};        // bytes per n-row
        cuuint32_t box[2]     = {64, 64};                    // 64 k (128B = SW128) x 64 n
        cuuint32_t estr[2]    = {1, 1};
        enc(&tmapB, CU_TENSOR_MAP_DATA_TYPE_FLOAT16, 2, wtPtr,
            dims, strides, box, estr,
            CU_TENSOR_MAP_INTERLEAVE_NONE, CU_TENSOR_MAP_SWIZZLE_128B,
            CU_TENSOR_MAP_L2_PROMOTION_L2_128B, CU_TENSOR_MAP_FLOAT_OOB_FILL_NONE);
    }

    pack_a_kernel<<<(BB * GK / 4) / 256, 256>>>(x, h);
    transpose_w_kernel<<<dim3(4096 / 32, 2048 / 32, 4), dim3(32, 8)>>>(W);
    lstm_gemm_tc<<<dim3(4, 32), 256, SMEM_BYTES>>>(tmapB, c, out);
}

// round 7
// speedup vs baseline: 1.1408x; 1.1408x over previous
#include <cuda_runtime.h>
#include <cuda_fp16.h>
#include <cuda.h>
#include <cstdint>
#include <math.h>

// ---------------- problem constants ----------------
#define BB   1024
#define UU   2048
#define GK   4096            // GEMM K = 2U
#define GN   8192            // GEMM N = 4U

// ---------------- arch gate ----------------
#if defined(__CUDA_ARCH__) && (defined(__CUDA_ARCH_FEAT_SM103_ALL) || \
                               defined(__CUDA_ARCH_FEAT_SM100_ALL) || \
                               defined(__CUDA_ARCH_FEAT_SM101_ALL))
#define HAS_TCGEN05 1
#else
#define HAS_TCGEN05 0
#endif

// ---------------- GEMM tiling ----------------
#define BM   256
#define BN   256
#define BK   64
#define NC   (GK / BK)       // 64 chunks
#define NSTAGE 3
#define CLUSTER_X 4

#define SMEM_TMEM_PTR 0
#define SMEM_FULL0    32     // full[s] = 32 + 8s
#define SMEM_DONE0    64     // done[s] = 64 + 8s
#define SMEM_ALLDONE  96     // single-phase completion barrier
#define SMEM_STAGE0   1024
#define STAGE_BYTES   65536
#define STAGE_B_OFF   32768
#define SMEM_BYTES    (1024 + NSTAGE * STAGE_BYTES)

// idesc kind::f16: F32 accum, f16 inputs, N=128, M=128
#define MMA_IDESC  ((1u << 4) | (16u << 17) | (8u << 24))

// ---------------- device scratch ----------------
__device__ __half g_Af16[(size_t)BB * GK];        // [1024][4096] packed xh fp16
__device__ __half g_Wt  [(size_t)GN * GK];        // [8192][4096] fp16 K-major, gate-permuted

// ---------------- generic helpers ----------------
__device__ __forceinline__ uint32_t smem_u32(const void* p) {
    uint32_t a;
    asm("{ .reg .u64 t; cvta.to.shared.u64 t, %1; cvt.u32.u64 %0, t; }" : "=r"(a) : "l"(p));
    return a;
}
__device__ __forceinline__ float sigmoidf_(float v) { return 1.f / (1.f + expf(-v)); }

// ================= preprocessing =================

__global__ void pack_a_kernel(const float* __restrict__ x, const float* __restrict__ h) {
    const int gi = blockIdx.x * blockDim.x + threadIdx.x;
    const int b  = gi >> 10;
    const int k  = (gi & 1023) * 4;
    const int ksp = k >> 11;
    const int d   = k & 2047;
    const float* src = (d < 1024) ? (x + (size_t)b * UU + ksp * 1024 + d)
                                  : (h + (size_t)b * UU + ksp * 1024 + (d - 1024));
    const float4 v = *reinterpret_cast<const float4*>(src);
    __half2 p0 = __floats2half2_rn(v.x, v.y);
    __half2 p1 = __floats2half2_rn(v.z, v.w);
    uint2 o;
    o.x = *reinterpret_cast<uint32_t*>(&p0);
    o.y = *reinterpret_cast<uint32_t*>(&p1);
    *reinterpret_cast<uint2*>(&g_Af16[(size_t)b * GK + k]) = o;
}

// W [ksp][nsp][d][f] fp32 -> Wt[n'][k] fp16 with gate permute n' = nsp*4096 + uu*4 + gate
__global__ void transpose_w_kernel(const float* __restrict__ W) {
    __shared__ float tile[32][33];
    const int ksp = blockIdx.z >> 1, nsp = blockIdx.z & 1;
    const int dBase = blockIdx.y * 32, fBase = blockIdx.x * 32;
    const float* src = W + ((size_t)(ksp * 2 + nsp) * 2048 + dBase) * 4096 + fBase;
    #pragma unroll
    for (int j = 0; j < 4; ++j) {
        const int r = threadIdx.y * 4 + j;
        tile[r][threadIdx.x] = src[(size_t)r * 4096 + threadIdx.x];
    }
    __syncthreads();
    const int gate = fBase >> 10;
    const int uu0  = fBase & 1023;
    #pragma unroll
    for (int j = 0; j < 4; ++j) {
        const int r = threadIdx.y * 4 + j;
        const int np = nsp * 4096 + (uu0 + r) * 4 + gate;
        g_Wt[(size_t)np * GK + ksp * 2048 + dBase + threadIdx.x] =
            __float2half_rn(tile[threadIdx.x][r]);
    }
}

// ================= arch-specific helpers =================
#if HAS_TCGEN05
__device__ __forceinline__ uint32_t elect_one() {
    uint32_t pred;
    asm volatile("{\n\t.reg .pred p;\n\telect.sync _|p, 0xFFFFFFFF;\n\t"
                 "selp.b32 %0, 1, 0, p;\n\t}" : "=r"(pred));
    return pred;
}
__device__ __forceinline__ uint32_t cl_rank() {
    uint32_t r; asm("mov.u32 %0, %%cluster_ctarank;" : "=r"(r)); return r;
}
#define DESC_BASE ((uint64_t(2) << 61) | (uint64_t(1) << 46) | (uint64_t(64) << 32) | (uint64_t(1) << 16))
#define MK_DESC(addr) (DESC_BASE | ((uint64_t)((addr) >> 4) & 0x3FFF))

__device__ __forceinline__ void mma_f16_ss(uint32_t d, uint64_t ad, uint64_t bd,
                                           uint32_t idesc, uint32_t en) {
    asm volatile(
        "{\n\t.reg .pred p;\n\tsetp.ne.u32 p, %4, 0;\n\t"
        "tcgen05.mma.cta_group::1.kind::f16 [%0], %1, %2, %3, {%5,%5,%5,%5}, p;\n\t}"
        :: "r"(d), "l"(ad), "l"(bd), "r"(idesc), "r"(en), "r"(0u) : "memory");
}
#define MBAR_INIT(a, c)  asm volatile("mbarrier.init.shared.b64 [%0], %1;" :: "r"(a), "r"(c) : "memory")
#define MBAR_EXPECT_TX(a, n) asm volatile("mbarrier.arrive.expect_tx.shared.b64 _, [%0], %1;" :: "r"(a), "r"(n) : "memory")
#define TC_COMMIT(a)     asm volatile("tcgen05.commit.cta_group::1.mbarrier::arrive::one.shared::cluster.b64 [%0];" :: "r"(a) : "memory")
#define TC_COMMIT_MC(a, mask) asm volatile( \
    "tcgen05.commit.cta_group::1.mbarrier::arrive::one.shared::cluster.multicast::cluster.b64 [%0], %1;" \
    :: "r"(a), "h"((uint16_t)(mask)) : "memory")
#define TC_ALLOC(sa, n)  asm volatile("tcgen05.alloc.cta_group::1.sync.aligned.shared::cta.b32 [%0], %1;" :: "r"(sa), "r"(n) : "memory")
#define TC_DEALLOC(t, n) asm volatile("tcgen05.dealloc.cta_group::1.sync.aligned.b32 %0, %1;" :: "r"(t), "r"(n))
#define TC_RELINQ()      asm volatile("tcgen05.relinquish_alloc_permit.cta_group::1.sync.aligned;")
#define TC_FENCE_AFTER() asm volatile("tcgen05.fence::after_thread_sync;" ::: "memory")
#define TC_WAIT_LD()     asm volatile("tcgen05.wait::ld.sync.aligned;" ::: "memory")
#define CLUSTER_SYNC()   do { \
    asm volatile("barrier.cluster.arrive.aligned;" ::: "memory"); \
    asm volatile("barrier.cluster.wait.aligned;" ::: "memory"); } while (0)

__device__ __forceinline__ void mbar_wait(uint32_t mbar, uint32_t parity) {
    asm volatile(
        "{\n\t.reg .pred P;\n\t"
        "W%=:\n\t"
        "mbarrier.try_wait.parity.acquire.cta.shared::cta.b64 P, [%0], %1, 0x989680;\n\t"
        "@P bra.uni D%=;\n\t"
        "bra.uni W%=;\n\t"
        "D%=:\n\t}"
        :: "r"(mbar), "r"(parity) : "memory");
}

__device__ __forceinline__ void tma2d(uint32_t dst, const void* tmap,
                                      int cx, int cy, uint32_t mbar) {
    asm volatile(
        "cp.async.bulk.tensor.2d.shared::cta.global.tile.mbarrier::complete_tx::bytes "
        "[%0], [%1, {%2, %3}], [%4];"
        :: "r"(dst), "l"(tmap), "r"(cx), "r"(cy), "r"(mbar) : "memory");
}
__device__ __forceinline__ void tma2d_mc(uint32_t dst, const void* tmap,
                                         int cx, int cy, uint32_t mbar, uint16_t mask) {
    asm volatile(
        "cp.async.bulk.tensor.2d.shared::cluster.global.tile.mbarrier::complete_tx::bytes.multicast::cluster "
        "[%0], [%1, {%2, %3}], [%4], %5;"
        :: "r"(dst), "l"(tmap), "r"(cx), "r"(cy), "r"(mbar), "h"(mask) : "memory");
}

__device__ __forceinline__ void ldtm32(uint32_t* r, uint32_t addr) {
    asm volatile(
        "tcgen05.ld.sync.aligned.32x32b.x32.b32 "
        "{%0,%1,%2,%3,%4,%5,%6,%7,%8,%9,%10,%11,%12,%13,%14,%15,"
        "%16,%17,%18,%19,%20,%21,%22,%23,%24,%25,%26,%27,%28,%29,%30,%31}, [%32];"
        : "=r"(r[0]), "=r"(r[1]), "=r"(r[2]), "=r"(r[3]), "=r"(r[4]), "=r"(r[5]), "=r"(r[6]), "=r"(r[7]),
          "=r"(r[8]), "=r"(r[9]), "=r"(r[10]), "=r"(r[11]), "=r"(r[12]), "=r"(r[13]), "=r"(r[14]), "=r"(r[15]),
          "=r"(r[16]), "=r"(r[17]), "=r"(r[18]), "=r"(r[19]), "=r"(r[20]), "=r"(r[21]), "=r"(r[22]), "=r"(r[23]),
          "=r"(r[24]), "=r"(r[25]), "=r"(r[26]), "=r"(r[27]), "=r"(r[28]), "=r"(r[29]), "=r"(r[30]), "=r"(r[31])
        : "r"(addr));
}
#endif

// ================= GEMM + fused gates: warp-specialized, full TMA =================
// grid (4, 32), cluster (4,1,1) along x: 4 cluster CTAs share blockIdx.y => same
// colBase => same B panel (multicast-shared); rowBase differs per rank.
__global__ __launch_bounds__(256, 1) __cluster_dims__(CLUSTER_X, 1, 1)
void lstm_gemm_tc(const __grid_constant__ CUtensorMap tmapA,
                  const __grid_constant__ CUtensorMap tmapB,
                  const float* __restrict__ c, float* __restrict__ out) {
#if HAS_TCGEN05
    extern __shared__ char smem_raw[];
    const uint32_t sbase = smem_u32(smem_raw);
    const int tid  = threadIdx.x;
    const int warp = tid >> 5;
    const int lane = tid & 31;
    const uint32_t rank = cl_rank();

    const int rowBase = blockIdx.x * BM;
    const int colBase = blockIdx.y * BN;

    if (warp == 0) { TC_ALLOC(sbase + SMEM_TMEM_PTR, 512); }
    else           { TC_RELINQ(); }
    __syncthreads();
    uint32_t tmem_base;
    asm volatile("ld.shared.b32 %0, [%1];" : "=r"(tmem_base) : "r"(sbase + SMEM_TMEM_PTR));

    if (tid == 0) {
        #pragma unroll
        for (int s = 0; s < NSTAGE; ++s) {
            MBAR_INIT(sbase + SMEM_FULL0 + 8 * s, 1);          // 1 expect_tx arrival per round
            MBAR_INIT(sbase + SMEM_DONE0 + 8 * s, CLUSTER_X);  // 4 commits per round
        }
        MBAR_INIT(sbase + SMEM_ALLDONE, 1);                    // single-phase, unambiguous
    }
    __syncthreads();
    CLUSTER_SYNC();   // barriers visible cluster-wide before any multicast traffic

    // ================= PRODUCER: warp 1, one thread =================
    if (warp == 1 && elect_one()) {
        for (int cc = 0; cc < NC; ++cc) {
            const uint32_t s = (uint32_t)(cc % NSTAGE);
            if (cc >= NSTAGE) {
                // previous occupant (cc-NSTAGE) fully consumed by ALL 4 CTAs.
                // Safe parity wait: done[s] count is always in {round, round+1} here.
                mbar_wait(sbase + SMEM_DONE0 + 8 * s, (uint32_t)(((cc - NSTAGE) / NSTAGE) & 1));
            }
            const uint32_t fullb = sbase + SMEM_FULL0 + 8 * s;
            const uint32_t stA = sbase + SMEM_STAGE0 + s * STAGE_BYTES;
            const uint32_t stB = stA + STAGE_B_OFF;
            MBAR_EXPECT_TX(fullb, (uint32_t)65536);           // A 32KB + B 4x8KB slices
            tma2d(stA,         &tmapA, cc * BK, rowBase,        fullb);
            tma2d(stA + 16384, &tmapA, cc * BK, rowBase + 128,  fullb);
            tma2d_mc(stB + rank * 8192, &tmapB, cc * BK, colBase + (int)rank * 64,
                     fullb, (uint16_t)0xF);
        }
    }

    // ================= CONSUMER: warp 0, one thread =================
    if (warp == 0 && elect_one()) {
        for (int it = 0; it < NC; ++it) {
            const uint32_t s = (uint32_t)(it % NSTAGE);
            mbar_wait(sbase + SMEM_FULL0 + 8 * s, (uint32_t)((it / NSTAGE) & 1));
            const uint32_t st = sbase + SMEM_STAGE0 + s * STAGE_BYTES;
            const uint64_t aD = MK_DESC(st);
            const uint64_t bD = MK_DESC(st + STAGE_B_OFF);
            #pragma unroll
            for (int m = 0; m < 2; ++m)
                #pragma unroll
                for (int hh = 0; hh < 2; ++hh) {
                    const uint32_t dcol = tmem_base + m * 256 + hh * 128;
                    #pragma unroll
                    for (int ks = 0; ks < 4; ++ks)
                        mma_f16_ss(dcol, aD + m * 1024 + ks * 2, bD + hh * 1024 + ks * 2,
                                   MMA_IDESC, (uint32_t)(it > 0 || ks > 0));
                }
            TC_COMMIT_MC(sbase + SMEM_DONE0 + 8 * s, 0xF);    // stage consumed, cluster-wide
        }
        // Fires when ALL local MMAs complete. Single phase -> parity 0 is exact.
        TC_COMMIT(sbase + SMEM_ALLDONE);
    }

    // everyone syncs (consumer has issued the alldone commit), then waits for
    // actual MMA completion on the single-phase barrier.
    __syncthreads();
    mbar_wait(sbase + SMEM_ALLDONE, 0u);
    TC_FENCE_AFTER();

    // ---- fused gate epilogue ----
    {
        const int m   = warp >> 2;
        const int sub = warp & 3;
        const int b   = rowBase + m * 128 + sub * 32 + lane;
        const int nsp    = colBase >> 12;
        const int uuBase = (colBase & 4095) >> 2;
        const float* cRow = c + (size_t)b * UU;
        float* outH = out + (size_t)b * UU;
        float* outC = out + (size_t)BB * UU + (size_t)b * UU;

        uint32_t regs[32];
        #pragma unroll
        for (int cb = 0; cb < 8; ++cb) {
            ldtm32(regs, tmem_base + m * 256 + cb * 32);
            TC_WAIT_LD();
            const int u0 = nsp * 1024 + uuBase + cb * 8;
            float cArr[8], hArr[8], nArr[8];
            *reinterpret_cast<float4*>(&cArr[0]) = *reinterpret_cast<const float4*>(cRow + u0);
            *reinterpret_cast<float4*>(&cArr[4]) = *reinterpret_cast<const float4*>(cRow + u0 + 4);
            #pragma unroll
            for (int j = 0; j < 8; ++j) {
                const float ig = sigmoidf_(__uint_as_float(regs[4 * j + 0]));
                const float fg = sigmoidf_(__uint_as_float(regs[4 * j + 1]));
                const float gg = tanhf(__uint_as_float(regs[4 * j + 2]));
                const float og = sigmoidf_(__uint_as_float(regs[4 * j + 3]));
                const float nc = fg * cArr[j] + ig * gg;
                nArr[j] = nc;
                hArr[j] = og * tanhf(nc);
            }
            *reinterpret_cast<float4*>(outH + u0)     = *reinterpret_cast<float4*>(&hArr[0]);
            *reinterpret_cast<float4*>(outH + u0 + 4) = *reinterpret_cast<float4*>(&hArr[4]);
            *reinterpret_cast<float4*>(outC + u0)     = *reinterpret_cast<float4*>(&nArr[0]);
            *reinterpret_cast<float4*>(outC + u0 + 4) = *reinterpret_cast<float4*>(&nArr[4]);
        }
    }

    // NOTE: no mbarrier.inval — peer commit-multicast arrivals may still be in
    // flight toward done[]; invalidating would fault. Exit needs no inval.
    __syncthreads();
    if (warp == 0) { TC_DEALLOC(tmem_base, 512); }
    CLUSTER_SYNC();   // no CTA exits while peer traffic may still target its smem

#else
    // ===== baseline-arch fallback (compile-correct; not selected on sm_103a) =====
    const int tid = threadIdx.x;
    const int rowBase = blockIdx.x * BM;
    const int colBase = blockIdx.y * BN;
    const int nsp    = colBase >> 12;
    const int uuBase = (colBase & 4095) >> 2;
    const int b = rowBase + tid;
    const __half* arow = g_Af16 + (size_t)b * GK;
    for (int j = 0; j < 64; ++j) {
        const __half* brow = g_Wt + (size_t)(colBase + j * 4) * GK;
        float acc[4] = {0.f, 0.f, 0.f, 0.f};
        for (int k = 0; k < GK; ++k) {
            const float a = __half2float(arow[k]);
            acc[0] += a * __half2float(brow[k]);
            acc[1] += a * __half2float(brow[(size_t)GK + k]);
            acc[2] += a * __half2float(brow[(size_t)2 * GK + k]);
            acc[3] += a * __half2float(brow[(size_t)3 * GK + k]);
        }
        const int u = nsp * 1024 + uuBase + j;
        const float ig = sigmoidf_(acc[0]);
        const float fg = sigmoidf_(acc[1]);
        const float gg = tanhf(acc[2]);
        const float og = sigmoidf_(acc[3]);
        const float cin = c[(size_t)b * UU + u];
        const float nc = fg * cin + ig * gg;
        out[(size_t)b * UU + u] = og * tanhf(nc);
        out[(size_t)BB * UU + (size_t)b * UU + u] = nc;
    }
#endif
}

// ================= launch =================
typedef CUresult (*PFN_encodeTiled_t)(
    CUtensorMap*, CUtensorMapDataType, cuuint32_t, void*,
    const cuuint64_t*, const cuuint64_t*, const cuuint32_t*, const cuuint32_t*,
    CUtensorMapInterleave, CUtensorMapSwizzle, CUtensorMapL2promotion,
    CUtensorMapFloatOOBfill);

extern "C" void kernel_launch(void* const* d_in, const int* in_sizes, int n_in,
                              void* d_out, int out_size) {
    const float* x = (const float*)d_in[0];
    const float* h = (const float*)d_in[1];
    const float* c = (const float*)d_in[2];
    const float* W = (const float*)d_in[3];
    float* out = (float*)d_out;

    cudaFuncSetAttribute(lstm_gemm_tc, cudaFuncAttributeMaxDynamicSharedMemorySize, SMEM_BYTES);

    void* fn = nullptr;
    cudaDriverEntryPointQueryResult qres;
    cudaGetDriverEntryPoint("cuTensorMapEncodeTiled", &fn, cudaEnableDefault, &qres);
    PFN_encodeTiled_t enc = (PFN_encodeTiled_t)fn;

    // A tensormap: g_Af16 [1024 rows][4096 k] fp16, box [64 k x 128 rows], SW128
    CUtensorMap tmapA;
    {
        void* aPtr = nullptr;
        cudaGetSymbolAddress(&aPtr, g_Af16);
        cuuint64_t dims[2]    = {GK, BB};
        cuuint64_t strides[1] = {(cuuint64_t)GK * 2};
        cuuint32_t box[2]     = {64, 128};
        cuuint32_t estr[2]    = {1, 1};
        enc(&tmapA, CU_TENSOR_MAP_DATA_TYPE_FLOAT16, 2, aPtr,
            dims, strides, box, estr,
            CU_TENSOR_MAP_INTERLEAVE_NONE, CU_TENSOR_MAP_SWIZZLE_128B,
            CU_TENSOR_MAP_L2_PROMOTION_L2_128B, CU_TENSOR_MAP_FLOAT_OOB_FILL_NONE);
    }
    // B tensormap: g_Wt [8192 n][4096 k] fp16, box [64 k x 64 n], SW128
    CUtensorMap tmapB;
    {
        void* wtPtr = nullptr;
        cudaGetSymbolAddress(&wtPtr, g_Wt);
        cuuint64_t dims[2]    = {GK, GN};
        cuuint64_t strides[1] = {(cuuint64_t)GK * 2};
        cuuint32_t box[2]     = {64, 64};
        cuuint32_t estr[2]    = {1, 1};
        enc(&tmapB, CU_TENSOR_MAP_DATA_TYPE_FLOAT16, 2, wtPtr,
            dims, strides, box, estr,
            CU_TENSOR_MAP_INTERLEAVE_NONE, CU_TENSOR_MAP_SWIZZLE_128B,
            CU_TENSOR_MAP_L2_PROMOTION_L2_128B, CU_TENSOR_MAP_FLOAT_OOB_FILL_NONE);
    }

    pack_a_kernel<<<(BB * GK / 4) / 256, 256>>>(x, h);
    transpose_w_kernel<<<dim3(4096 / 32, 2048 / 32, 4), dim3(32, 8)>>>(W);
    lstm_gemm_tc<<<dim3(4, 32), 256, SMEM_BYTES>>>(tmapA, tmapB, c, out);
}

// round 8
// speedup vs baseline: 1.2067x; 1.0578x over previous
#include <cuda_runtime.h>
#include <cuda_fp16.h>
#include <cuda.h>
#include <cstdint>
#include <math.h>

// ---------------- problem constants ----------------
#define BB   1024
#define UU   2048
#define GK   4096            // GEMM K = 2U
#define GN   8192            // GEMM N = 4U

// ---------------- arch gate ----------------
#if defined(__CUDA_ARCH__) && (defined(__CUDA_ARCH_FEAT_SM103_ALL) || \
                               defined(__CUDA_ARCH_FEAT_SM100_ALL) || \
                               defined(__CUDA_ARCH_FEAT_SM101_ALL))
#define HAS_TCGEN05 1
#else
#define HAS_TCGEN05 0
#endif

// ---------------- GEMM tiling ----------------
#define BM   256
#define BN   256
#define BK   64
#define NC   (GK / BK)       // 64 chunks
#define NSTAGE 3
#define CLUSTER_X 4

#define SMEM_TMEM_PTR 0
#define SMEM_FULL0    32     // full[s] = 32 + 8s
#define SMEM_DONE0    64     // done[s] = 64 + 8s
#define SMEM_ALLDONE  96     // single-phase completion barrier
#define SMEM_STAGE0   1024
#define STAGE_BYTES   65536
#define STAGE_B_OFF   32768
#define SMEM_BYTES    (1024 + NSTAGE * STAGE_BYTES)

// idesc kind::f16: F32 accum, f16 inputs, N=128, M=128
#define MMA_IDESC  ((1u << 4) | (16u << 17) | (8u << 24))

// prep kernel split
#define NTBLK 16384          // transpose blocks: 64 dT x 64 fT x 4 zz
#define NPBLK 4096           // pack blocks
#define NPREP (NTBLK + NPBLK)

// ---------------- device scratch ----------------
__device__ __half g_Af16[(size_t)BB * GK];        // [1024][4096] packed xh fp16
__device__ __half g_Wt  [(size_t)GN * GK];        // [8192][4096] fp16 K-major, gate-permuted

// ---------------- generic helpers ----------------
__device__ __forceinline__ uint32_t smem_u32(const void* p) {
    uint32_t a;
    asm("{ .reg .u64 t; cvta.to.shared.u64 t, %1; cvt.u32.u64 %0, t; }" : "=r"(a) : "l"(p));
    return a;
}
__device__ __forceinline__ float sigmoidf_(float v) { return 1.f / (1.f + expf(-v)); }

// ================= fused preprocessing =================
// blocks [0, NTBLK):  W transpose+convert+gate-permute, 32d x 64f tiles, vectorized
// blocks [NTBLK, NPREP): pack xh -> fp16
__global__ __launch_bounds__(256)
void prep_kernel(const float* __restrict__ x, const float* __restrict__ h,
                 const float* __restrict__ W) {
    const int bid = blockIdx.x;
    const int tid = threadIdx.x;

    if (bid < NTBLK) {
        __shared__ float tile[32][68];              // 68-float rows: 16B-aligned, col reads 4-way max
        const int zz  = bid >> 12;                  // (ksp*2 + nsp)
        const int rem = bid & 4095;
        const int dT  = rem >> 6;                   // 64 d-tiles of 32
        const int fT  = rem & 63;                   // 64 f-tiles of 64
        const int ksp = zz >> 1, nsp = zz & 1;
        const int dBase = dT * 32, fBase = fT * 64;
        const float* src = W + ((size_t)zz * 2048 + dBase) * 4096 + fBase;

        // load 32 rows x 64 floats = 512 float4, 2 per thread (coalesced 256B/warp)
        #pragma unroll
        for (int p = 0; p < 2; ++p) {
            const int idx = tid + 256 * p;
            const int r  = idx >> 4;
            const int c4 = idx & 15;
            const float4 v = *reinterpret_cast<const float4*>(src + (size_t)r * 4096 + c4 * 4);
            *reinterpret_cast<float4*>(&tile[r][c4 * 4]) = v;
        }
        __syncthreads();

        // write: 64 f-rows x 8 half4 chunks (32 k each row-segment)
        const int gate = fBase >> 10;               // f = gate*1024 + uu
        const int uu0  = fBase & 1023;
        #pragma unroll
        for (int p = 0; p < 2; ++p) {
            const int idx = tid + 256 * p;
            const int i  = idx >> 3;                // f offset in tile (0..63)
            const int r0 = (idx & 7) * 4;           // d chunk base (0..28)
            const float a0 = tile[r0 + 0][i];
            const float a1 = tile[r0 + 1][i];
            const float a2 = tile[r0 + 2][i];
            const float a3 = tile[r0 + 3][i];
            __half2 h0 = __floats2half2_rn(a0, a1);
            __half2 h1 = __floats2half2_rn(a2, a3);
            uint2 o;
            o.x = *reinterpret_cast<uint32_t*>(&h0);
            o.y = *reinterpret_cast<uint32_t*>(&h1);
            const int np = nsp * 4096 + (uu0 + i) * 4 + gate;     // gate-permuted column
            *reinterpret_cast<uint2*>(&g_Wt[(size_t)np * GK + ksp * 2048 + dBase + r0]) = o;
        }
    } else {
        // ---- pack xh -> fp16 [1024][4096] ----
        const int gi = (bid - NTBLK) * 256 + tid;   // float4 group
        const int b  = gi >> 10;
        const int k  = (gi & 1023) * 4;
        const int ksp = k >> 11;
        const int d   = k & 2047;
        const float* src = (d < 1024) ? (x + (size_t)b * UU + ksp * 1024 + d)
                                      : (h + (size_t)b * UU + ksp * 1024 + (d - 1024));
        const float4 v = *reinterpret_cast<const float4*>(src);
        __half2 p0 = __floats2half2_rn(v.x, v.y);
        __half2 p1 = __floats2half2_rn(v.z, v.w);
        uint2 o;
        o.x = *reinterpret_cast<uint32_t*>(&p0);
        o.y = *reinterpret_cast<uint32_t*>(&p1);
        *reinterpret_cast<uint2*>(&g_Af16[(size_t)b * GK + k]) = o;
    }
}

// ================= arch-specific helpers =================
#if HAS_TCGEN05
__device__ __forceinline__ uint32_t elect_one() {
    uint32_t pred;
    asm volatile("{\n\t.reg .pred p;\n\telect.sync _|p, 0xFFFFFFFF;\n\t"
                 "selp.b32 %0, 1, 0, p;\n\t}" : "=r"(pred));
    return pred;
}
__device__ __forceinline__ uint32_t cl_rank() {
    uint32_t r; asm("mov.u32 %0, %%cluster_ctarank;" : "=r"(r)); return r;
}
#define DESC_BASE ((uint64_t(2) << 61) | (uint64_t(1) << 46) | (uint64_t(64) << 32) | (uint64_t(1) << 16))
#define MK_DESC(addr) (DESC_BASE | ((uint64_t)((addr) >> 4) & 0x3FFF))

__device__ __forceinline__ void mma_f16_ss(uint32_t d, uint64_t ad, uint64_t bd,
                                           uint32_t idesc, uint32_t en) {
    asm volatile(
        "{\n\t.reg .pred p;\n\tsetp.ne.u32 p, %4, 0;\n\t"
        "tcgen05.mma.cta_group::1.kind::f16 [%0], %1, %2, %3, {%5,%5,%5,%5}, p;\n\t}"
        :: "r"(d), "l"(ad), "l"(bd), "r"(idesc), "r"(en), "r"(0u) : "memory");
}
#define MBAR_INIT(a, c)  asm volatile("mbarrier.init.shared.b64 [%0], %1;" :: "r"(a), "r"(c) : "memory")
#define MBAR_EXPECT_TX(a, n) asm volatile("mbarrier.arrive.expect_tx.shared.b64 _, [%0], %1;" :: "r"(a), "r"(n) : "memory")
#define TC_COMMIT(a)     asm volatile("tcgen05.commit.cta_group::1.mbarrier::arrive::one.shared::cluster.b64 [%0];" :: "r"(a) : "memory")
#define TC_COMMIT_MC(a, mask) asm volatile( \
    "tcgen05.commit.cta_group::1.mbarrier::arrive::one.shared::cluster.multicast::cluster.b64 [%0], %1;" \
    :: "r"(a), "h"((uint16_t)(mask)) : "memory")
#define TC_ALLOC(sa, n)  asm volatile("tcgen05.alloc.cta_group::1.sync.aligned.shared::cta.b32 [%0], %1;" :: "r"(sa), "r"(n) : "memory")
#define TC_DEALLOC(t, n) asm volatile("tcgen05.dealloc.cta_group::1.sync.aligned.b32 %0, %1;" :: "r"(t), "r"(n))
#define TC_RELINQ()      asm volatile("tcgen05.relinquish_alloc_permit.cta_group::1.sync.aligned;")
#define TC_FENCE_AFTER() asm volatile("tcgen05.fence::after_thread_sync;" ::: "memory")
#define TC_WAIT_LD()     asm volatile("tcgen05.wait::ld.sync.aligned;" ::: "memory")
#define CLUSTER_SYNC()   do { \
    asm volatile("barrier.cluster.arrive.aligned;" ::: "memory"); \
    asm volatile("barrier.cluster.wait.aligned;" ::: "memory"); } while (0)

__device__ __forceinline__ void mbar_wait(uint32_t mbar, uint32_t parity) {
    asm volatile(
        "{\n\t.reg .pred P;\n\t"
        "W%=:\n\t"
        "mbarrier.try_wait.parity.acquire.cta.shared::cta.b64 P, [%0], %1, 0x989680;\n\t"
        "@P bra.uni D%=;\n\t"
        "bra.uni W%=;\n\t"
        "D%=:\n\t}"
        :: "r"(mbar), "r"(parity) : "memory");
}

__device__ __forceinline__ void tma2d(uint32_t dst, const void* tmap,
                                      int cx, int cy, uint32_t mbar) {
    asm volatile(
        "cp.async.bulk.tensor.2d.shared::cta.global.tile.mbarrier::complete_tx::bytes "
        "[%0], [%1, {%2, %3}], [%4];"
        :: "r"(dst), "l"(tmap), "r"(cx), "r"(cy), "r"(mbar) : "memory");
}
__device__ __forceinline__ void tma2d_mc(uint32_t dst, const void* tmap,
                                         int cx, int cy, uint32_t mbar, uint16_t mask) {
    asm volatile(
        "cp.async.bulk.tensor.2d.shared::cluster.global.tile.mbarrier::complete_tx::bytes.multicast::cluster "
        "[%0], [%1, {%2, %3}], [%4], %5;"
        :: "r"(dst), "l"(tmap), "r"(cx), "r"(cy), "r"(mbar), "h"(mask) : "memory");
}

__device__ __forceinline__ void ldtm32(uint32_t* r, uint32_t addr) {
    asm volatile(
        "tcgen05.ld.sync.aligned.32x32b.x32.b32 "
        "{%0,%1,%2,%3,%4,%5,%6,%7,%8,%9,%10,%11,%12,%13,%14,%15,"
        "%16,%17,%18,%19,%20,%21,%22,%23,%24,%25,%26,%27,%28,%29,%30,%31}, [%32];"
        : "=r"(r[0]), "=r"(r[1]), "=r"(r[2]), "=r"(r[3]), "=r"(r[4]), "=r"(r[5]), "=r"(r[6]), "=r"(r[7]),
          "=r"(r[8]), "=r"(r[9]), "=r"(r[10]), "=r"(r[11]), "=r"(r[12]), "=r"(r[13]), "=r"(r[14]), "=r"(r[15]),
          "=r"(r[16]), "=r"(r[17]), "=r"(r[18]), "=r"(r[19]), "=r"(r[20]), "=r"(r[21]), "=r"(r[22]), "=r"(r[23]),
          "=r"(r[24]), "=r"(r[25]), "=r"(r[26]), "=r"(r[27]), "=r"(r[28]), "=r"(r[29]), "=r"(r[30]), "=r"(r[31])
        : "r"(addr));
}
#endif

// ================= GEMM + fused gates: warp-specialized, full TMA =================
// grid (4, 32), cluster (4,1,1) along x: cluster CTAs share blockIdx.y => same
// colBase => same B panel (multicast-shared); rowBase differs per rank.
__global__ __launch_bounds__(256, 1) __cluster_dims__(CLUSTER_X, 1, 1)
void lstm_gemm_tc(const __grid_constant__ CUtensorMap tmapA,
                  const __grid_constant__ CUtensorMap tmapB,
                  const float* __restrict__ c, float* __restrict__ out) {
#if HAS_TCGEN05
    extern __shared__ char smem_raw[];
    const uint32_t sbase = smem_u32(smem_raw);
    const int tid  = threadIdx.x;
    const int warp = tid >> 5;
    const int lane = tid & 31;
    const uint32_t rank = cl_rank();

    const int rowBase = blockIdx.x * BM;
    const int colBase = blockIdx.y * BN;

    if (warp == 0) { TC_ALLOC(sbase + SMEM_TMEM_PTR, 512); }
    else           { TC_RELINQ(); }
    __syncthreads();
    uint32_t tmem_base;
    asm volatile("ld.shared.b32 %0, [%1];" : "=r"(tmem_base) : "r"(sbase + SMEM_TMEM_PTR));

    if (tid == 0) {
        #pragma unroll
        for (int s = 0; s < NSTAGE; ++s) {
            MBAR_INIT(sbase + SMEM_FULL0 + 8 * s, 1);          // 1 expect_tx arrival per round
            MBAR_INIT(sbase + SMEM_DONE0 + 8 * s, CLUSTER_X);  // 4 commits per round
        }
        MBAR_INIT(sbase + SMEM_ALLDONE, 1);                    // single-phase, unambiguous
    }
    __syncthreads();
    CLUSTER_SYNC();   // barriers visible cluster-wide before any multicast traffic

    // ================= PRODUCER: warp 1, one thread =================
    if (warp == 1 && elect_one()) {
        for (int cc = 0; cc < NC; ++cc) {
            const uint32_t s = (uint32_t)(cc % NSTAGE);
            if (cc >= NSTAGE) {
                mbar_wait(sbase + SMEM_DONE0 + 8 * s, (uint32_t)(((cc - NSTAGE) / NSTAGE) & 1));
            }
            const uint32_t fullb = sbase + SMEM_FULL0 + 8 * s;
            const uint32_t stA = sbase + SMEM_STAGE0 + s * STAGE_BYTES;
            const uint32_t stB = stA + STAGE_B_OFF;
            MBAR_EXPECT_TX(fullb, (uint32_t)65536);           // A 32KB + B 4x8KB slices
            tma2d(stA,         &tmapA, cc * BK, rowBase,        fullb);
            tma2d(stA + 16384, &tmapA, cc * BK, rowBase + 128,  fullb);
            tma2d_mc(stB + rank * 8192, &tmapB, cc * BK, colBase + (int)rank * 64,
                     fullb, (uint16_t)0xF);
        }
    }

    // ================= CONSUMER: warp 0, one thread =================
    if (warp == 0 && elect_one()) {
        for (int it = 0; it < NC; ++it) {
            const uint32_t s = (uint32_t)(it % NSTAGE);
            mbar_wait(sbase + SMEM_FULL0 + 8 * s, (uint32_t)((it / NSTAGE) & 1));
            const uint32_t st = sbase + SMEM_STAGE0 + s * STAGE_BYTES;
            const uint64_t aD = MK_DESC(st);
            const uint64_t bD = MK_DESC(st + STAGE_B_OFF);
            #pragma unroll
            for (int m = 0; m < 2; ++m)
                #pragma unroll
                for (int hh = 0; hh < 2; ++hh) {
                    const uint32_t dcol = tmem_base + m * 256 + hh * 128;
                    #pragma unroll
                    for (int ks = 0; ks < 4; ++ks)
                        mma_f16_ss(dcol, aD + m * 1024 + ks * 2, bD + hh * 1024 + ks * 2,
                                   MMA_IDESC, (uint32_t)(it > 0 || ks > 0));
                }
            TC_COMMIT_MC(sbase + SMEM_DONE0 + 8 * s, 0xF);    // stage consumed, cluster-wide
        }
        TC_COMMIT(sbase + SMEM_ALLDONE);                      // fires when ALL local MMAs done
    }

    __syncthreads();
    mbar_wait(sbase + SMEM_ALLDONE, 0u);
    TC_FENCE_AFTER();

    // ---- fused gate epilogue ----
    {
        const int m   = warp >> 2;
        const int sub = warp & 3;
        const int b   = rowBase + m * 128 + sub * 32 + lane;
        const int nsp    = colBase >> 12;
        const int uuBase = (colBase & 4095) >> 2;
        const float* cRow = c + (size_t)b * UU;
        float* outH = out + (size_t)b * UU;
        float* outC = out + (size_t)BB * UU + (size_t)b * UU;

        uint32_t regs[32];
        #pragma unroll
        for (int cb = 0; cb < 8; ++cb) {
            ldtm32(regs, tmem_base + m * 256 + cb * 32);
            TC_WAIT_LD();
            const int u0 = nsp * 1024 + uuBase + cb * 8;
            float cArr[8], hArr[8], nArr[8];
            *reinterpret_cast<float4*>(&cArr[0]) = *reinterpret_cast<const float4*>(cRow + u0);
            *reinterpret_cast<float4*>(&cArr[4]) = *reinterpret_cast<const float4*>(cRow + u0 + 4);
            #pragma unroll
            for (int j = 0; j < 8; ++j) {
                const float ig = sigmoidf_(__uint_as_float(regs[4 * j + 0]));
                const float fg = sigmoidf_(__uint_as_float(regs[4 * j + 1]));
                const float gg = tanhf(__uint_as_float(regs[4 * j + 2]));
                const float og = sigmoidf_(__uint_as_float(regs[4 * j + 3]));
                const float nc = fg * cArr[j] + ig * gg;
                nArr[j] = nc;
                hArr[j] = og * tanhf(nc);
            }
            *reinterpret_cast<float4*>(outH + u0)     = *reinterpret_cast<float4*>(&hArr[0]);
            *reinterpret_cast<float4*>(outH + u0 + 4) = *reinterpret_cast<float4*>(&hArr[4]);
            *reinterpret_cast<float4*>(outC + u0)     = *reinterpret_cast<float4*>(&nArr[0]);
            *reinterpret_cast<float4*>(outC + u0 + 4) = *reinterpret_cast<float4*>(&nArr[4]);
        }
    }

    // no mbarrier.inval — peer commit-multicast arrivals may still be in flight.
    __syncthreads();
    if (warp == 0) { TC_DEALLOC(tmem_base, 512); }
    CLUSTER_SYNC();   // no CTA exits while peer traffic may still target its smem

#else
    // ===== baseline-arch fallback (compile-correct; not selected on sm_103a) =====
    const int tid = threadIdx.x;
    const int rowBase = blockIdx.x * BM;
    const int colBase = blockIdx.y * BN;
    const int nsp    = colBase >> 12;
    const int uuBase = (colBase & 4095) >> 2;
    const int b = rowBase + tid;
    const __half* arow = g_Af16 + (size_t)b * GK;
    for (int j = 0; j < 64; ++j) {
        const __half* brow = g_Wt + (size_t)(colBase + j * 4) * GK;
        float acc[4] = {0.f, 0.f, 0.f, 0.f};
        for (int k = 0; k < GK; ++k) {
            const float a = __half2float(arow[k]);
            acc[0] += a * __half2float(brow[k]);
            acc[1] += a * __half2float(brow[(size_t)GK + k]);
            acc[2] += a * __half2float(brow[(size_t)2 * GK + k]);
            acc[3] += a * __half2float(brow[(size_t)3 * GK + k]);
        }
        const int u = nsp * 1024 + uuBase + j;
        const float ig = sigmoidf_(acc[0]);
        const float fg = sigmoidf_(acc[1]);
        const float gg = tanhf(acc[2]);
        const float og = sigmoidf_(acc[3]);
        const float cin = c[(size_t)b * UU + u];
        const float nc = fg * cin + ig * gg;
        out[(size_t)b * UU + u] = og * tanhf(nc);
        out[(size_t)BB * UU + (size_t)b * UU + u] = nc;
    }
#endif
}

// ================= launch =================
typedef CUresult (*PFN_encodeTiled_t)(
    CUtensorMap*, CUtensorMapDataType, cuuint32_t, void*,
    const cuuint64_t*, const cuuint64_t*, const cuuint32_t*, const cuuint32_t*,
    CUtensorMapInterleave, CUtensorMapSwizzle, CUtensorMapL2promotion,
    CUtensorMapFloatOOBfill);

extern "C" void kernel_launch(void* const* d_in, const int* in_sizes, int n_in,
                              void* d_out, int out_size) {
    const float* x = (const float*)d_in[0];
    const float* h = (const float*)d_in[1];
    const float* c = (const float*)d_in[2];
    const float* W = (const float*)d_in[3];
    float* out = (float*)d_out;

    cudaFuncSetAttribute(lstm_gemm_tc, cudaFuncAttributeMaxDynamicSharedMemorySize, SMEM_BYTES);

    void* fn = nullptr;
    cudaDriverEntryPointQueryResult qres;
    cudaGetDriverEntryPoint("cuTensorMapEncodeTiled", &fn, cudaEnableDefault, &qres);
    PFN_encodeTiled_t enc = (PFN_encodeTiled_t)fn;

    // A tensormap: g_Af16 [1024 rows][4096 k] fp16, box [64 k x 128 rows], SW128
    CUtensorMap tmapA;
    {
        void* aPtr = nullptr;
        cudaGetSymbolAddress(&aPtr, g_Af16);
        cuuint64_t dims[2]    = {GK, BB};
        cuuint64_t strides[1] = {(cuuint64_t)GK * 2};
        cuuint32_t box[2]     = {64, 128};
        cuuint32_t estr[2]    = {1, 1};
        enc(&tmapA, CU_TENSOR_MAP_DATA_TYPE_FLOAT16, 2, aPtr,
            dims, strides, box, estr,
            CU_TENSOR_MAP_INTERLEAVE_NONE, CU_TENSOR_MAP_SWIZZLE_128B,
            CU_TENSOR_MAP_L2_PROMOTION_L2_128B, CU_TENSOR_MAP_FLOAT_OOB_FILL_NONE);
    }
    // B tensormap: g_Wt [8192 n][4096 k] fp16, box [64 k x 64 n], SW128
    CUtensorMap tmapB;
    {
        void* wtPtr = nullptr;
        cudaGetSymbolAddress(&wtPtr, g_Wt);
        cuuint64_t dims[2]    = {GK, GN};
        cuuint64_t strides[1] = {(cuuint64_t)GK * 2};
        cuuint32_t box[2]     = {64, 64};
        cuuint32_t estr[2]    = {1, 1};
        enc(&tmapB, CU_TENSOR_MAP_DATA_TYPE_FLOAT16, 2, wtPtr,
            dims, strides, box, estr,
            CU_TENSOR_MAP_INTERLEAVE_NONE, CU_TENSOR_MAP_SWIZZLE_128B,
            CU_TENSOR_MAP_L2_PROMOTION_L2_128B, CU_TENSOR_MAP_FLOAT_OOB_FILL_NONE);
    }

    prep_kernel<<<NPREP, 256>>>(x, h, W);
    lstm_gemm_tc<<<dim3(4, 32), 256, SMEM_BYTES>>>(tmapA, tmapB, c, out);
}